// round 3
// baseline (speedup 1.0000x reference)
#include <cuda_runtime.h>
#include <math.h>

#define NTHREADS 256

__device__ __forceinline__ float lrelu(float x) { return x > 0.f ? x : 0.1f * x; }
__device__ __forceinline__ float sigmoidf_(float x) { return 1.f / (1.f + expf(-x)); }

__global__ __launch_bounds__(NTHREADS) void policy_kernel(
    const int*   __restrict__ Nmat,   // [B,56] int32
    const float* __restrict__ adj,    // [B,3,48,48]
    const float* __restrict__ W1,  const float* __restrict__ b1,
    const float* __restrict__ W2,  const float* __restrict__ b2,
    const float* __restrict__ asW, const float* __restrict__ asb,
    const float* __restrict__ atW, const float* __restrict__ atb,
    const float* __restrict__ l1W, const float* __restrict__ l1b,
    const float* __restrict__ l2W, const float* __restrict__ l2b,
    const float* __restrict__ f1,  const float* __restrict__ f2,
    const float* __restrict__ s1,  const float* __restrict__ s2,
    const float* __restrict__ e1,  const float* __restrict__ e2,
    const float* __restrict__ t1W, const float* __restrict__ t1b,
    const float* __restrict__ t2W, const float* __restrict__ t2b,
    const float* __restrict__ v1W, const float* __restrict__ v1b,
    const float* __restrict__ v2W, const float* __restrict__ v2b,
    const float* __restrict__ v3W, const float* __restrict__ v3b,
    float* __restrict__ out)
{
    __shared__ float s_buf[6144];    // adj plane (2304) -> h1/h (48x128)
    __shared__ float s_asum[2304];   // Asum; later reused for small buffers
    __shared__ float s_h2[3072];     // h2 -> h_out (48x64)
    __shared__ float s_rinv[48];
    __shared__ int   s_node[56];

    // overlays on s_asum (Asum is dead after GEMM3)
    float* s_gp   = s_asum;          // 512 gate partials
    float* s_g    = s_asum + 512;    // 128
    float* s_t1   = s_asum + 640;    // 128
    float* s_hf   = s_asum + 768;    // 64
    float* s_hid  = s_asum + 832;    // 160
    float* s_o1   = s_asum + 992;    // 56
    float* s_o2   = s_asum + 1048;   // 56
    float* s_oe   = s_asum + 1104;   // 4
    float* s_ot   = s_asum + 1108;   // 4
    float* s_v2   = s_asum + 1112;   // 16
    float* s_misc = s_asum + 1128;   // 8

    const int b   = blockIdx.x;
    const int tid = threadIdx.x;

    if (tid < 56) s_node[tid] = Nmat[b * 56 + tid];

    // Zero asum accumulators (same thread->idx mapping as the accumulation loop)
    for (int idx = tid; idx < 2304; idx += NTHREADS) s_asum[idx] = 0.f;

    // ---- Phase 1: Asum = sum_r adj[r]*deg[r] (stream planes through smem) ----
    const float* adjb = adj + (size_t)b * 6912;
    for (int r = 0; r < 3; r++) {
        __syncthreads();  // previous plane consumers done
        const float4* a4 = (const float4*)(adjb + r * 2304);
        float4* p4 = (float4*)s_buf;
        for (int i = tid; i < 576; i += NTHREADS) p4[i] = a4[i];
        __syncthreads();
        if (tid < 48) {
            float s = 0.f;
            #pragma unroll
            for (int j = 0; j < 48; j++) s += s_buf[tid * 48 + j];
            s_rinv[tid] = 1.f / (s + 1.f);
        }
        __syncthreads();
        for (int idx = tid; idx < 2304; idx += NTHREADS)
            s_asum[idx] += s_buf[idx] * s_rinv[idx / 48];
    }
    __syncthreads();

    // ---- h1 = W1[node[j]] + b1  -> s_buf as [48][128] ----
    for (int idx = tid; idx < 6144; idx += NTHREADS) {
        int j = idx >> 7, d = idx & 127;
        s_buf[idx] = W1[s_node[j] * 128 + d] + b1[d];
    }
    __syncthreads();

    // ---- GEMM1: h = tanh(Asum @ h1 + h1), in place in s_buf ----
    {
        const int rg = tid >> 4, cg = tid & 15;
        const int i0 = rg * 3, d0 = cg * 8;
        float acc[3][8];
        #pragma unroll
        for (int r = 0; r < 3; r++)
            #pragma unroll
            for (int c = 0; c < 8; c++) acc[r][c] = 0.f;
        #pragma unroll 2
        for (int j = 0; j < 48; j++) {
            float a0 = s_asum[(i0 + 0) * 48 + j];
            float a1 = s_asum[(i0 + 1) * 48 + j];
            float a2 = s_asum[(i0 + 2) * 48 + j];
            const float4 h0  = *(const float4*)&s_buf[j * 128 + d0];
            const float4 h1v = *(const float4*)&s_buf[j * 128 + d0 + 4];
            float hv[8] = {h0.x, h0.y, h0.z, h0.w, h1v.x, h1v.y, h1v.z, h1v.w};
            #pragma unroll
            for (int c = 0; c < 8; c++) {
                acc[0][c] += a0 * hv[c];
                acc[1][c] += a1 * hv[c];
                acc[2][c] += a2 * hv[c];
            }
        }
        float res[3][8];
        #pragma unroll
        for (int r = 0; r < 3; r++) {
            const float4 p0 = *(const float4*)&s_buf[(i0 + r) * 128 + d0];
            const float4 p1 = *(const float4*)&s_buf[(i0 + r) * 128 + d0 + 4];
            res[r][0] = p0.x; res[r][1] = p0.y; res[r][2] = p0.z; res[r][3] = p0.w;
            res[r][4] = p1.x; res[r][5] = p1.y; res[r][6] = p1.z; res[r][7] = p1.w;
        }
        __syncthreads();
        #pragma unroll
        for (int r = 0; r < 3; r++)
            #pragma unroll
            for (int c = 0; c < 8; c++)
                s_buf[(i0 + r) * 128 + d0 + c] = tanhf(acc[r][c] + res[r][c]);
    }
    __syncthreads();

    // ---- GEMM2: h2 = h @ W2 + b2 -> s_h2 [48][64] ----
    {
        const int rg = tid >> 4, cg = tid & 15;
        const int i0 = rg * 3, d0 = cg * 4;
        const float4 bv = *(const float4*)&b2[d0];
        float acc[3][4];
        #pragma unroll
        for (int r = 0; r < 3; r++) { acc[r][0] = bv.x; acc[r][1] = bv.y; acc[r][2] = bv.z; acc[r][3] = bv.w; }
        for (int k4 = 0; k4 < 32; k4++) {
            float hr[3][4];
            #pragma unroll
            for (int r = 0; r < 3; r++) {
                float4 h = *(const float4*)&s_buf[(i0 + r) * 128 + k4 * 4];
                hr[r][0] = h.x; hr[r][1] = h.y; hr[r][2] = h.z; hr[r][3] = h.w;
            }
            float wk[4][4];
            #pragma unroll
            for (int kk = 0; kk < 4; kk++) {
                float4 w = *(const float4*)&W2[(k4 * 4 + kk) * 64 + d0];
                wk[kk][0] = w.x; wk[kk][1] = w.y; wk[kk][2] = w.z; wk[kk][3] = w.w;
            }
            #pragma unroll
            for (int r = 0; r < 3; r++)
                #pragma unroll
                for (int c = 0; c < 4; c++)
                    #pragma unroll
                    for (int kk = 0; kk < 4; kk++)
                        acc[r][c] += hr[r][kk] * wk[kk][c];
        }
        #pragma unroll
        for (int r = 0; r < 3; r++)
            *(float4*)&s_h2[(i0 + r) * 64 + d0] = make_float4(acc[r][0], acc[r][1], acc[r][2], acc[r][3]);
    }
    __syncthreads();

    // ---- GEMM3: h_out = tanh(Asum @ h2 + h2), in place in s_h2 ----
    {
        const int rg = tid >> 4, cg = tid & 15;
        const int i0 = rg * 3, d0 = cg * 4;
        float acc[3][4];
        #pragma unroll
        for (int r = 0; r < 3; r++)
            #pragma unroll
            for (int c = 0; c < 4; c++) acc[r][c] = 0.f;
        #pragma unroll 2
        for (int j = 0; j < 48; j++) {
            float a0 = s_asum[(i0 + 0) * 48 + j];
            float a1 = s_asum[(i0 + 1) * 48 + j];
            float a2 = s_asum[(i0 + 2) * 48 + j];
            float4 hv = *(const float4*)&s_h2[j * 64 + d0];
            float hc[4] = {hv.x, hv.y, hv.z, hv.w};
            #pragma unroll
            for (int c = 0; c < 4; c++) {
                acc[0][c] += a0 * hc[c];
                acc[1][c] += a1 * hc[c];
                acc[2][c] += a2 * hc[c];
            }
        }
        float rr[3][4];
        #pragma unroll
        for (int r = 0; r < 3; r++) {
            float4 p = *(const float4*)&s_h2[(i0 + r) * 64 + d0];
            rr[r][0] = p.x; rr[r][1] = p.y; rr[r][2] = p.z; rr[r][3] = p.w;
        }
        __syncthreads();
        #pragma unroll
        for (int r = 0; r < 3; r++)
            #pragma unroll
            for (int c = 0; c < 4; c++)
                s_h2[(i0 + r) * 64 + d0 + c] = tanhf(acc[r][c] + rr[r][c]);
    }
    __syncthreads();

    // ---- Gate: g = tanh( sum_i sigmoid(ann@asW+asb) * tanh(ann@atW+atb) ) ----
    // ann = [h_out (48x64) | onehot(node) (48x9)]; onehot part is a row-gather of W[64+node].
    {
        const int dg = (tid & 63) * 2;   // two d-columns per thread
        const int q  = tid >> 6;         // node quarter
        const int i0 = q * 12;
        float aS0[12], aS1[12], aT0[12], aT1[12];
        #pragma unroll
        for (int ii = 0; ii < 12; ii++) { aS0[ii] = 0.f; aS1[ii] = 0.f; aT0[ii] = 0.f; aT1[ii] = 0.f; }
        for (int k = 0; k < 64; k++) {
            float2 ws = *(const float2*)&asW[k * 128 + dg];
            float2 wt = *(const float2*)&atW[k * 128 + dg];
            #pragma unroll
            for (int ii = 0; ii < 12; ii++) {
                float hv = s_h2[(i0 + ii) * 64 + k];   // warp-broadcast LDS
                aS0[ii] += hv * ws.x; aS1[ii] += hv * ws.y;
                aT0[ii] += hv * wt.x; aT1[ii] += hv * wt.y;
            }
        }
        float2 sb = *(const float2*)&asb[dg];
        float2 tb = *(const float2*)&atb[dg];
        float sum0 = 0.f, sum1 = 0.f;
        #pragma unroll
        for (int ii = 0; ii < 12; ii++) {
            int nd = s_node[i0 + ii];
            float2 wso = *(const float2*)&asW[(64 + nd) * 128 + dg];
            float2 wto = *(const float2*)&atW[(64 + nd) * 128 + dg];
            float sg0 = aS0[ii] + wso.x + sb.x;
            float sg1 = aS1[ii] + wso.y + sb.y;
            float tg0 = aT0[ii] + wto.x + tb.x;
            float tg1 = aT1[ii] + wto.y + tb.y;
            sum0 += sigmoidf_(sg0) * tanhf(tg0);
            sum1 += sigmoidf_(sg1) * tanhf(tg1);
        }
        s_gp[q * 128 + dg]     = sum0;
        s_gp[q * 128 + dg + 1] = sum1;
    }
    __syncthreads();
    if (tid < 128)
        s_g[tid] = tanhf(s_gp[tid] + s_gp[128 + tid] + s_gp[256 + tid] + s_gp[384 + tid]);
    __syncthreads();

    // ---- hfeat = (g @ l1W + l1b) @ l2W + l2b  (no activation between) ----
    if (tid < 128) {
        float acc = l1b[tid];
        #pragma unroll 4
        for (int k = 0; k < 128; k++) acc += s_g[k] * l1W[k * 128 + tid];
        s_t1[tid] = acc;
    }
    __syncthreads();
    if (tid < 64) {
        float acc = l2b[tid];
        #pragma unroll 4
        for (int k = 0; k < 128; k++) acc += s_t1[k] * l2W[k * 64 + tid];
        s_hf[tid] = acc;
    }
    __syncthreads();

    // ---- Heads stage A: five 64->32 matvecs with leaky-relu ----
    if (tid < 160) {
        const int head = tid >> 5, u = tid & 31;
        const float* Wm;
        float acc;
        if      (head == 0) { Wm = f1;  acc = 0.f; }
        else if (head == 1) { Wm = s1;  acc = 0.f; }
        else if (head == 2) { Wm = e1;  acc = 0.f; }
        else if (head == 3) { Wm = t1W; acc = t1b[u]; }
        else                { Wm = v1W; acc = v1b[u]; }
        #pragma unroll 4
        for (int k = 0; k < 64; k++) acc += s_hf[k] * Wm[k * 32 + u];
        s_hid[tid] = lrelu(acc);
    }
    __syncthreads();

    // ---- Heads stage B ----
    if (tid < 56) {
        float acc = 0.f;
        #pragma unroll
        for (int u = 0; u < 32; u++) acc += s_hid[u] * f2[u * 56 + tid];
        bool ex = (s_node[tid] > 0) && (tid < 48);
        s_o1[tid] = acc + (ex ? 0.f : -10000.f);
    } else if (tid < 112) {
        int j = tid - 56;
        float acc = 0.f;
        #pragma unroll
        for (int u = 0; u < 32; u++) acc += s_hid[32 + u] * s2[u * 56 + j];
        s_o2[j] = acc;
    } else if (tid < 115) {
        int j = tid - 112;
        float acc = 0.f;
        #pragma unroll
        for (int u = 0; u < 32; u++) acc += s_hid[64 + u] * e2[u * 3 + j];
        s_oe[j] = acc;
    } else if (tid < 117) {
        int j = tid - 115;
        float acc = t2b[j];
        #pragma unroll
        for (int u = 0; u < 32; u++) acc += s_hid[96 + u] * t2W[u * 2 + j];
        s_ot[j] = acc;
    } else if (tid < 133) {
        int m = tid - 117;
        float acc = v2b[m];
        #pragma unroll
        for (int u = 0; u < 32; u++) acc += s_hid[128 + u] * v2W[u * 16 + m];
        s_v2[m] = lrelu(acc);
    }
    __syncthreads();

    // ---- Softmaxes / argmax / value ----
    if (tid == 0) {
        float acc = v3b[0];
        #pragma unroll
        for (int m = 0; m < 16; m++) acc += s_v2[m] * v3W[m];
        s_misc[0] = acc;                       // value

        float mx = s_o1[0]; int am = 0;        // argmax (first-max tie-break)
        for (int j = 1; j < 56; j++) { float v = s_o1[j]; if (v > mx) { mx = v; am = j; } }
        s_misc[1] = mx;
        ((int*)s_misc)[2] = am;

        float me = fmaxf(s_oe[0], fmaxf(s_oe[1], s_oe[2]));
        float e0 = expf(s_oe[0] - me), e1v = expf(s_oe[1] - me), e2v = expf(s_oe[2] - me);
        float inv = 1.f / (e0 + e1v + e2v);
        s_oe[0] = e0 * inv; s_oe[1] = e1v * inv; s_oe[2] = e2v * inv;

        float mt = fmaxf(s_ot[0], s_ot[1]);
        float p0 = expf(s_ot[0] - mt), p1 = expf(s_ot[1] - mt);
        float invt = 1.f / (p0 + p1);
        s_ot[0] = p0 * invt; s_ot[1] = p1 * invt;
    }
    __syncthreads();
    {
        int first = ((int*)s_misc)[2];
        if (tid < 56) {
            s_o1[tid] = expf(s_o1[tid] - s_misc[1]);
            bool ex2 = ((((s_node[tid] > 0) && (tid < 48)) || (tid >= 48)) && (tid != first));
            s_o2[tid] += (ex2 ? 0.f : -10000.f);
        }
    }
    __syncthreads();
    if (tid == 0) {
        float s = 0.f;
        for (int j = 0; j < 56; j++) s += s_o1[j];
        s_misc[3] = 1.f / s;
        float mx = s_o2[0];
        for (int j = 1; j < 56; j++) mx = fmaxf(mx, s_o2[j]);
        s_misc[4] = mx;
    }
    __syncthreads();
    if (tid < 56) s_o2[tid] = expf(s_o2[tid] - s_misc[4]);
    __syncthreads();
    if (tid == 0) {
        float s = 0.f;
        for (int j = 0; j < 56; j++) s += s_o2[j];
        s_misc[5] = 1.f / s;
    }
    __syncthreads();

    float* ob = out + (size_t)b * 118;
    if (tid < 56) {
        ob[tid] = s_o1[tid] * s_misc[3];
    } else if (tid >= 64 && tid < 120) {
        int j = tid - 64;
        ob[56 + j] = s_o2[j] * s_misc[5];
    } else if (tid == 128) {
        ob[112] = s_oe[0]; ob[113] = s_oe[1]; ob[114] = s_oe[2];
        ob[115] = s_ot[0]; ob[116] = s_ot[1]; ob[117] = s_misc[0];
    }
}

extern "C" void kernel_launch(void* const* d_in, const int* in_sizes, int n_in,
                              void* d_out, int out_size) {
    (void)in_sizes; (void)n_in; (void)out_size;
    policy_kernel<<<8192, NTHREADS>>>(
        (const int*)  d_in[0],  (const float*)d_in[1],
        (const float*)d_in[2],  (const float*)d_in[3],
        (const float*)d_in[4],  (const float*)d_in[5],
        (const float*)d_in[6],  (const float*)d_in[7],
        (const float*)d_in[8],  (const float*)d_in[9],
        (const float*)d_in[10], (const float*)d_in[11],
        (const float*)d_in[12], (const float*)d_in[13],
        (const float*)d_in[14], (const float*)d_in[15],
        (const float*)d_in[16], (const float*)d_in[17],
        (const float*)d_in[18], (const float*)d_in[19],
        (const float*)d_in[20], (const float*)d_in[21],
        (const float*)d_in[22], (const float*)d_in[23],
        (const float*)d_in[24], (const float*)d_in[25],
        (const float*)d_in[26], (const float*)d_in[27],
        (const float*)d_in[28], (const float*)d_in[29],
        (float*)d_out);
}

// round 5
// speedup vs baseline: 1.2229x; 1.2229x over previous
#include <cuda_runtime.h>
#include <math.h>

#define NTHREADS 256

typedef unsigned long long u64;

__device__ __forceinline__ u64 pk2(float x, float y) {
    u64 r; asm("mov.b64 %0, {%1,%2};" : "=l"(r) : "f"(x), "f"(y)); return r;
}
__device__ __forceinline__ u64 bc2(float x) { return pk2(x, x); }
__device__ __forceinline__ u64 f2fma(u64 a, u64 b, u64 c) {
    u64 d; asm("fma.rn.f32x2 %0, %1, %2, %3;" : "=l"(d) : "l"(a), "l"(b), "l"(c)); return d;
}
__device__ __forceinline__ float2 up2(u64 v) {
    float lo, hi; asm("mov.b64 {%0,%1}, %2;" : "=f"(lo), "=f"(hi) : "l"(v));
    return make_float2(lo, hi);
}

__device__ __forceinline__ float lrelu(float x) { return x > 0.f ? x : 0.1f * x; }
__device__ __forceinline__ float fsig(float x) {
    return __fdividef(1.f, 1.f + __expf(-x));
}
__device__ __forceinline__ float ftanh(float x) {
    return 1.f - __fdividef(2.f, __expf(2.f * x) + 1.f);
}

__global__ __launch_bounds__(NTHREADS, 3) void policy_kernel(
    const int*   __restrict__ Nmat,   // [B,56] int32
    const float* __restrict__ adj,    // [B,3,48,48]
    const float* __restrict__ W1,  const float* __restrict__ b1,
    const float* __restrict__ W2,  const float* __restrict__ b2,
    const float* __restrict__ asW, const float* __restrict__ asb,
    const float* __restrict__ atW, const float* __restrict__ atb,
    const float* __restrict__ l1W, const float* __restrict__ l1b,
    const float* __restrict__ l2W, const float* __restrict__ l2b,
    const float* __restrict__ f1,  const float* __restrict__ f2,
    const float* __restrict__ s1,  const float* __restrict__ s2,
    const float* __restrict__ e1,  const float* __restrict__ e2,
    const float* __restrict__ t1W, const float* __restrict__ t1b,
    const float* __restrict__ t2W, const float* __restrict__ t2b,
    const float* __restrict__ v1W, const float* __restrict__ v1b,
    const float* __restrict__ v2W, const float* __restrict__ v2b,
    const float* __restrict__ v3W, const float* __restrict__ v3b,
    float* __restrict__ out)
{
    __shared__ float s_buf[6144];    // adj plane -> h (48x128) -> hT (64x48)
    __shared__ float s_asum[2304];   // AsumT[j][i]; overlaid by tail buffers
    __shared__ float s_h2[3072];     // h2 (48x64)
    __shared__ float s_rinv[48];
    __shared__ int   s_node[56];

    // overlays on s_asum (AsumT dead after GEMM3)
    float* s_gp   = s_asum;          // 512 gate / matvec partials
    float* s_g    = s_asum + 512;    // 128
    float* s_t1   = s_asum + 640;    // 128
    float* s_hf   = s_asum + 768;    // 64
    float* s_hid  = s_asum + 832;    // 160
    float* s_o1   = s_asum + 992;    // 56
    float* s_o2   = s_asum + 1048;   // 56
    float* s_oe   = s_asum + 1104;   // 4
    float* s_ot   = s_asum + 1108;   // 4
    float* s_v2   = s_asum + 1112;   // 16
    float* s_misc = s_asum + 1128;   // 8

    const int b   = blockIdx.x;
    const int tid = threadIdx.x;

    if (tid < 56) s_node[tid] = Nmat[b * 56 + tid];

    // ---- Phase 1: AsumT[j][i] = sum_r adj[r][i][j] / (rowsum[r][i]+1) ----
    {
        float a_acc[9];
        #pragma unroll
        for (int t = 0; t < 9; t++) a_acc[t] = 0.f;
        const float* adjb = adj + (size_t)b * 6912;
        for (int r = 0; r < 3; r++) {
            __syncthreads();
            const float4* a4 = (const float4*)(adjb + r * 2304);
            float4* p4 = (float4*)s_buf;
            for (int i = tid; i < 576; i += NTHREADS) p4[i] = a4[i];
            __syncthreads();
            if (tid < 48) {
                const float4* row = (const float4*)&s_buf[tid * 48];
                float s = 0.f;
                #pragma unroll
                for (int t = 0; t < 12; t++) {
                    float4 v = row[t];
                    s += (v.x + v.y) + (v.z + v.w);
                }
                s_rinv[tid] = 1.f / (s + 1.f);
            }
            __syncthreads();
            #pragma unroll
            for (int t = 0; t < 9; t++) {
                int idx = tid + t * NTHREADS;
                a_acc[t] += s_buf[idx] * s_rinv[idx / 48];
            }
        }
        __syncthreads();
        #pragma unroll
        for (int t = 0; t < 9; t++) {
            int idx = tid + t * NTHREADS;
            int i = idx / 48, j = idx - i * 48;
            s_asum[j * 48 + i] = a_acc[t];
        }
    }
    __syncthreads();

    // ---- h1 = W1[node[j]] + b1  -> s_buf as [48][128] ----
    for (int t = tid; t < 1536; t += NTHREADS) {
        int j = t >> 5, d4 = (t & 31) << 2;
        float4 w = *(const float4*)&W1[s_node[j] * 128 + d4];
        float4 bb = *(const float4*)&b1[d4];
        *(float4*)&s_buf[j * 128 + d4] =
            make_float4(w.x + bb.x, w.y + bb.y, w.z + bb.z, w.w + bb.w);
    }
    __syncthreads();

    // ---- GEMM1: h = tanh(AsumT^T @ h1 + h1), in place in s_buf ----
    {
        const bool act = tid < 192;
        const int ig = tid >> 4, cg = tid & 15;
        const int i0 = ig * 4, d0 = cg * 8;
        u64 acc[4][4];
        #pragma unroll
        for (int i = 0; i < 4; i++)
            #pragma unroll
            for (int p = 0; p < 4; p++) acc[i][p] = 0ull;
        if (act) {
            #pragma unroll 2
            for (int j = 0; j < 48; j++) {
                float4 aT = *(const float4*)&s_asum[j * 48 + i0];
                ulonglong2 h01 = *(const ulonglong2*)&s_buf[j * 128 + d0];
                ulonglong2 h23 = *(const ulonglong2*)&s_buf[j * 128 + d0 + 4];
                u64 hp0 = h01.x, hp1 = h01.y, hp2 = h23.x, hp3 = h23.y;
                float av[4] = {aT.x, aT.y, aT.z, aT.w};
                #pragma unroll
                for (int i = 0; i < 4; i++) {
                    u64 aa = bc2(av[i]);
                    acc[i][0] = f2fma(aa, hp0, acc[i][0]);
                    acc[i][1] = f2fma(aa, hp1, acc[i][1]);
                    acc[i][2] = f2fma(aa, hp2, acc[i][2]);
                    acc[i][3] = f2fma(aa, hp3, acc[i][3]);
                }
            }
        }
        __syncthreads();
        if (act) {
            #pragma unroll
            for (int i = 0; i < 4; i++) {
                float* row = &s_buf[(i0 + i) * 128 + d0];
                float4 r0 = *(const float4*)row;
                float4 r1 = *(const float4*)(row + 4);
                float2 a0 = up2(acc[i][0]), a1 = up2(acc[i][1]);
                float2 a2 = up2(acc[i][2]), a3 = up2(acc[i][3]);
                *(float4*)row = make_float4(ftanh(a0.x + r0.x), ftanh(a0.y + r0.y),
                                            ftanh(a1.x + r0.z), ftanh(a1.y + r0.w));
                *(float4*)(row + 4) = make_float4(ftanh(a2.x + r1.x), ftanh(a2.y + r1.y),
                                                  ftanh(a3.x + r1.z), ftanh(a3.y + r1.w));
            }
        }
    }
    __syncthreads();

    // ---- GEMM2: h2 = h @ W2 + b2 -> s_h2 [48][64] ----
    {
        const int rg = tid >> 4, cg = tid & 15;
        const int i0 = rg * 3, d0 = cg * 4;
        float4 bv = *(const float4*)&b2[d0];
        u64 acc[3][2];
        #pragma unroll
        for (int r = 0; r < 3; r++) { acc[r][0] = pk2(bv.x, bv.y); acc[r][1] = pk2(bv.z, bv.w); }
        for (int k4 = 0; k4 < 32; k4++) {
            float4 hr[3];
            #pragma unroll
            for (int r = 0; r < 3; r++)
                hr[r] = *(const float4*)&s_buf[(i0 + r) * 128 + k4 * 4];
            #pragma unroll
            for (int kk = 0; kk < 4; kk++) {
                ulonglong2 w2 = *(const ulonglong2*)&W2[(k4 * 4 + kk) * 64 + d0];
                float hk[3] = { kk == 0 ? hr[0].x : kk == 1 ? hr[0].y : kk == 2 ? hr[0].z : hr[0].w,
                                kk == 0 ? hr[1].x : kk == 1 ? hr[1].y : kk == 2 ? hr[1].z : hr[1].w,
                                kk == 0 ? hr[2].x : kk == 1 ? hr[2].y : kk == 2 ? hr[2].z : hr[2].w };
                #pragma unroll
                for (int r = 0; r < 3; r++) {
                    u64 hb = bc2(hk[r]);
                    acc[r][0] = f2fma(hb, w2.x, acc[r][0]);
                    acc[r][1] = f2fma(hb, w2.y, acc[r][1]);
                }
            }
        }
        #pragma unroll
        for (int r = 0; r < 3; r++) {
            float2 a0 = up2(acc[r][0]), a1 = up2(acc[r][1]);
            *(float4*)&s_h2[(i0 + r) * 64 + d0] = make_float4(a0.x, a0.y, a1.x, a1.y);
        }
    }
    __syncthreads();

    // ---- GEMM3: h_outT[d][i] = tanh(AsumT^T @ h2 + h2) -> s_buf [64][48] ----
    {
        const bool act = tid < 192;
        if (act) {
            const int ig = tid >> 4, cg = tid & 15;
            const int i0 = ig * 4, d0 = cg * 4;
            u64 acc[4][2];
            #pragma unroll
            for (int i = 0; i < 4; i++) { acc[i][0] = 0ull; acc[i][1] = 0ull; }
            #pragma unroll 2
            for (int j = 0; j < 48; j++) {
                float4 aT = *(const float4*)&s_asum[j * 48 + i0];
                ulonglong2 hj = *(const ulonglong2*)&s_h2[j * 64 + d0];
                float av[4] = {aT.x, aT.y, aT.z, aT.w};
                #pragma unroll
                for (int i = 0; i < 4; i++) {
                    u64 aa = bc2(av[i]);
                    acc[i][0] = f2fma(aa, hj.x, acc[i][0]);
                    acc[i][1] = f2fma(aa, hj.y, acc[i][1]);
                }
            }
            float4 rr[4];
            #pragma unroll
            for (int i = 0; i < 4; i++)
                rr[i] = *(const float4*)&s_h2[(i0 + i) * 64 + d0];
            float2 a0[4], a1[4];
            #pragma unroll
            for (int i = 0; i < 4; i++) { a0[i] = up2(acc[i][0]); a1[i] = up2(acc[i][1]); }
            *(float4*)&s_buf[(d0 + 0) * 48 + i0] =
                make_float4(ftanh(a0[0].x + rr[0].x), ftanh(a0[1].x + rr[1].x),
                            ftanh(a0[2].x + rr[2].x), ftanh(a0[3].x + rr[3].x));
            *(float4*)&s_buf[(d0 + 1) * 48 + i0] =
                make_float4(ftanh(a0[0].y + rr[0].y), ftanh(a0[1].y + rr[1].y),
                            ftanh(a0[2].y + rr[2].y), ftanh(a0[3].y + rr[3].y));
            *(float4*)&s_buf[(d0 + 2) * 48 + i0] =
                make_float4(ftanh(a1[0].x + rr[0].z), ftanh(a1[1].x + rr[1].z),
                            ftanh(a1[2].x + rr[2].z), ftanh(a1[3].x + rr[3].z));
            *(float4*)&s_buf[(d0 + 3) * 48 + i0] =
                make_float4(ftanh(a1[0].y + rr[0].w), ftanh(a1[1].y + rr[1].w),
                            ftanh(a1[2].y + rr[2].w), ftanh(a1[3].y + rr[3].w));
        }
    }
    __syncthreads();

    // ---- Gate: g = tanh( sum_i sigmoid(ann@asW+asb) * tanh(ann@atW+atb) ) ----
    // h_outT in s_buf [64][48]; onehot part = row-gather of W[64+node].
    {
        const int dg = (tid & 63) * 2;
        const int q  = tid >> 6;
        const int i0 = q * 12;
        u64 aS[12], aT[12];
        #pragma unroll
        for (int ii = 0; ii < 12; ii++) { aS[ii] = 0ull; aT[ii] = 0ull; }
        for (int k = 0; k < 64; k++) {
            u64 ws = *(const u64*)&asW[k * 128 + dg];
            u64 wt = *(const u64*)&atW[k * 128 + dg];
            float4 h0 = *(const float4*)&s_buf[k * 48 + i0];
            float4 h4 = *(const float4*)&s_buf[k * 48 + i0 + 4];
            float4 h8 = *(const float4*)&s_buf[k * 48 + i0 + 8];
            float hv[12] = {h0.x, h0.y, h0.z, h0.w, h4.x, h4.y, h4.z, h4.w,
                            h8.x, h8.y, h8.z, h8.w};
            #pragma unroll
            for (int ii = 0; ii < 12; ii++) {
                u64 hb = bc2(hv[ii]);
                aS[ii] = f2fma(hb, ws, aS[ii]);
                aT[ii] = f2fma(hb, wt, aT[ii]);
            }
        }
        float2 sb = *(const float2*)&asb[dg];
        float2 tb = *(const float2*)&atb[dg];
        float sum0 = 0.f, sum1 = 0.f;
        #pragma unroll
        for (int ii = 0; ii < 12; ii++) {
            int nd = s_node[i0 + ii];
            float2 wso = *(const float2*)&asW[(64 + nd) * 128 + dg];
            float2 wto = *(const float2*)&atW[(64 + nd) * 128 + dg];
            float2 vS = up2(aS[ii]);
            float2 vT = up2(aT[ii]);
            float sg0 = vS.x + wso.x + sb.x;
            float sg1 = vS.y + wso.y + sb.y;
            float tg0 = vT.x + wto.x + tb.x;
            float tg1 = vT.y + wto.y + tb.y;
            sum0 += fsig(sg0) * ftanh(tg0);
            sum1 += fsig(sg1) * ftanh(tg1);
        }
        s_gp[q * 128 + dg]     = sum0;
        s_gp[q * 128 + dg + 1] = sum1;
    }
    __syncthreads();
    if (tid < 128)
        s_g[tid] = ftanh(s_gp[tid] + s_gp[128 + tid] + s_gp[256 + tid] + s_gp[384 + tid]);
    __syncthreads();

    // ---- hfeat = (g @ l1W + l1b) @ l2W + l2b  (k-split matvecs) ----
    {
        int c = tid & 127, half = tid >> 7;
        float acc = 0.f;
        int k0 = half * 64;
        #pragma unroll 4
        for (int k = 0; k < 64; k++) acc += s_g[k0 + k] * l1W[(k0 + k) * 128 + c];
        s_gp[half * 128 + c] = acc;
    }
    __syncthreads();
    if (tid < 128) s_t1[tid] = l1b[tid] + s_gp[tid] + s_gp[128 + tid];
    __syncthreads();
    {
        int c = tid & 63, qq = tid >> 6;
        float acc = 0.f;
        int k0 = qq * 32;
        #pragma unroll 4
        for (int k = 0; k < 32; k++) acc += s_t1[k0 + k] * l2W[(k0 + k) * 64 + c];
        s_gp[qq * 64 + c] = acc;
    }
    __syncthreads();
    if (tid < 64)
        s_hf[tid] = l2b[tid] + s_gp[tid] + s_gp[64 + tid] + s_gp[128 + tid] + s_gp[192 + tid];
    __syncthreads();

    // ---- Heads stage A: five 64->32 matvecs with leaky-relu ----
    if (tid < 160) {
        const int head = tid >> 5, u = tid & 31;
        const float* Wm;
        float acc;
        if      (head == 0) { Wm = f1;  acc = 0.f; }
        else if (head == 1) { Wm = s1;  acc = 0.f; }
        else if (head == 2) { Wm = e1;  acc = 0.f; }
        else if (head == 3) { Wm = t1W; acc = t1b[u]; }
        else                { Wm = v1W; acc = v1b[u]; }
        #pragma unroll 4
        for (int k = 0; k < 64; k++) acc += s_hf[k] * Wm[k * 32 + u];
        s_hid[tid] = lrelu(acc);
    }
    __syncthreads();

    // ---- Heads stage B ----
    if (tid < 56) {
        float acc = 0.f;
        #pragma unroll
        for (int u = 0; u < 32; u++) acc += s_hid[u] * f2[u * 56 + tid];
        bool ex = (s_node[tid] > 0) && (tid < 48);
        s_o1[tid] = acc + (ex ? 0.f : -10000.f);
    } else if (tid < 112) {
        int j = tid - 56;
        float acc = 0.f;
        #pragma unroll
        for (int u = 0; u < 32; u++) acc += s_hid[32 + u] * s2[u * 56 + j];
        s_o2[j] = acc;
    } else if (tid < 115) {
        int j = tid - 112;
        float acc = 0.f;
        #pragma unroll
        for (int u = 0; u < 32; u++) acc += s_hid[64 + u] * e2[u * 3 + j];
        s_oe[j] = acc;
    } else if (tid < 117) {
        int j = tid - 115;
        float acc = t2b[j];
        #pragma unroll
        for (int u = 0; u < 32; u++) acc += s_hid[96 + u] * t2W[u * 2 + j];
        s_ot[j] = acc;
    } else if (tid < 133) {
        int m = tid - 117;
        float acc = v2b[m];
        #pragma unroll
        for (int u = 0; u < 32; u++) acc += s_hid[128 + u] * v2W[u * 16 + m];
        s_v2[m] = lrelu(acc);
    }
    __syncthreads();

    // ---- Softmaxes / argmax / value ----
    if (tid == 0) {
        float acc = v3b[0];
        #pragma unroll
        for (int m = 0; m < 16; m++) acc += s_v2[m] * v3W[m];
        s_misc[0] = acc;                       // value

        float mx = s_o1[0]; int am = 0;        // argmax (first-max tie-break)
        for (int j = 1; j < 56; j++) { float v = s_o1[j]; if (v > mx) { mx = v; am = j; } }
        s_misc[1] = mx;
        ((int*)s_misc)[2] = am;

        float me = fmaxf(s_oe[0], fmaxf(s_oe[1], s_oe[2]));
        float e0 = __expf(s_oe[0] - me), e1v = __expf(s_oe[1] - me), e2v = __expf(s_oe[2] - me);
        float inv = 1.f / (e0 + e1v + e2v);
        s_oe[0] = e0 * inv; s_oe[1] = e1v * inv; s_oe[2] = e2v * inv;

        float mt = fmaxf(s_ot[0], s_ot[1]);
        float p0 = __expf(s_ot[0] - mt), p1 = __expf(s_ot[1] - mt);
        float invt = 1.f / (p0 + p1);
        s_ot[0] = p0 * invt; s_ot[1] = p1 * invt;
    }
    __syncthreads();
    {
        int first = ((int*)s_misc)[2];
        if (tid < 56) {
            s_o1[tid] = __expf(s_o1[tid] - s_misc[1]);
            bool ex2 = ((((s_node[tid] > 0) && (tid < 48)) || (tid >= 48)) && (tid != first));
            s_o2[tid] += (ex2 ? 0.f : -10000.f);
        }
    }
    __syncthreads();
    if (tid == 0) {
        float s = 0.f;
        for (int j = 0; j < 56; j++) s += s_o1[j];
        s_misc[3] = 1.f / s;
        float mx = s_o2[0];
        for (int j = 1; j < 56; j++) mx = fmaxf(mx, s_o2[j]);
        s_misc[4] = mx;
    }
    __syncthreads();
    if (tid < 56) s_o2[tid] = __expf(s_o2[tid] - s_misc[4]);
    __syncthreads();
    if (tid == 0) {
        float s = 0.f;
        for (int j = 0; j < 56; j++) s += s_o2[j];
        s_misc[5] = 1.f / s;
    }
    __syncthreads();

    float* ob = out + (size_t)b * 118;
    if (tid < 56) {
        ob[tid] = s_o1[tid] * s_misc[3];
    } else if (tid >= 64 && tid < 120) {
        int j = tid - 64;
        ob[56 + j] = s_o2[j] * s_misc[5];
    } else if (tid == 128) {
        ob[112] = s_oe[0]; ob[113] = s_oe[1]; ob[114] = s_oe[2];
        ob[115] = s_ot[0]; ob[116] = s_ot[1]; ob[117] = s_misc[0];
    }
}

extern "C" void kernel_launch(void* const* d_in, const int* in_sizes, int n_in,
                              void* d_out, int out_size) {
    (void)in_sizes; (void)n_in; (void)out_size;
    policy_kernel<<<8192, NTHREADS>>>(
        (const int*)  d_in[0],  (const float*)d_in[1],
        (const float*)d_in[2],  (const float*)d_in[3],
        (const float*)d_in[4],  (const float*)d_in[5],
        (const float*)d_in[6],  (const float*)d_in[7],
        (const float*)d_in[8],  (const float*)d_in[9],
        (const float*)d_in[10], (const float*)d_in[11],
        (const float*)d_in[12], (const float*)d_in[13],
        (const float*)d_in[14], (const float*)d_in[15],
        (const float*)d_in[16], (const float*)d_in[17],
        (const float*)d_in[18], (const float*)d_in[19],
        (const float*)d_in[20], (const float*)d_in[21],
        (const float*)d_in[22], (const float*)d_in[23],
        (const float*)d_in[24], (const float*)d_in[25],
        (const float*)d_in[26], (const float*)d_in[27],
        (const float*)d_in[28], (const float*)d_in[29],
        (float*)d_out);
}

// round 6
// speedup vs baseline: 1.2245x; 1.0013x over previous
#include <cuda_runtime.h>
#include <math.h>

#define NTHREADS 256
#define HSTRIDE 132   // padded stride for h1/h [48][132] (bank-conflict fix)
#define TSTRIDE 50    // padded stride for h_outT [64][50]

typedef unsigned long long u64;

__device__ __forceinline__ u64 pk2(float x, float y) {
    u64 r; asm("mov.b64 %0, {%1,%2};" : "=l"(r) : "f"(x), "f"(y)); return r;
}
__device__ __forceinline__ u64 bc2(float x) { return pk2(x, x); }
__device__ __forceinline__ u64 f2fma(u64 a, u64 b, u64 c) {
    u64 d; asm("fma.rn.f32x2 %0, %1, %2, %3;" : "=l"(d) : "l"(a), "l"(b), "l"(c)); return d;
}
__device__ __forceinline__ float2 up2(u64 v) {
    float lo, hi; asm("mov.b64 {%0,%1}, %2;" : "=f"(lo), "=f"(hi) : "l"(v));
    return make_float2(lo, hi);
}

__device__ __forceinline__ float lrelu(float x) { return x > 0.f ? x : 0.1f * x; }
__device__ __forceinline__ float fsig(float x) {
    return __fdividef(1.f, 1.f + __expf(-x));
}
__device__ __forceinline__ float ftanh(float x) {
    return 1.f - __fdividef(2.f, __expf(2.f * x) + 1.f);
}

__global__ __launch_bounds__(NTHREADS, 3) void policy_kernel(
    const int*   __restrict__ Nmat,   // [B,56] int32
    const float* __restrict__ adj,    // [B,3,48,48]
    const float* __restrict__ W1,  const float* __restrict__ b1,
    const float* __restrict__ W2,  const float* __restrict__ b2,
    const float* __restrict__ asW, const float* __restrict__ asb,
    const float* __restrict__ atW, const float* __restrict__ atb,
    const float* __restrict__ l1W, const float* __restrict__ l1b,
    const float* __restrict__ l2W, const float* __restrict__ l2b,
    const float* __restrict__ f1,  const float* __restrict__ f2,
    const float* __restrict__ s1,  const float* __restrict__ s2,
    const float* __restrict__ e1,  const float* __restrict__ e2,
    const float* __restrict__ t1W, const float* __restrict__ t1b,
    const float* __restrict__ t2W, const float* __restrict__ t2b,
    const float* __restrict__ v1W, const float* __restrict__ v1b,
    const float* __restrict__ v2W, const float* __restrict__ v2b,
    const float* __restrict__ v3W, const float* __restrict__ v3b,
    float* __restrict__ out)
{
    __shared__ float s_buf[6336];    // adj plane -> h1/h [48][132] -> h_outT [64][50]
    __shared__ float s_asum[2304];   // AsumT[j][i] stride 48; overlaid by tail buffers
    __shared__ float s_h2[3072];     // h2 [48][64]
    __shared__ float s_rinv[48];
    __shared__ int   s_node[56];

    // overlays on s_asum (AsumT dead after GEMM3)
    float* s_gp   = s_asum;          // 1024 gate partials (8 x 128)
    float* s_g    = s_asum + 1024;   // 128
    float* s_t1   = s_asum + 1152;   // 128
    float* s_hf   = s_asum + 1280;   // 64
    float* s_hid  = s_asum + 1344;   // 160
    float* s_o1   = s_asum + 1504;   // 56
    float* s_o2   = s_asum + 1560;   // 56
    float* s_oe   = s_asum + 1616;   // 4
    float* s_ot   = s_asum + 1620;   // 4
    float* s_v2   = s_asum + 1624;   // 16
    float* s_misc = s_asum + 1640;   // 8

    const int b    = blockIdx.x;
    const int tid  = threadIdx.x;
    const int w    = tid >> 5;
    const int lane = tid & 31;

    if (tid < 56) s_node[tid] = Nmat[b * 56 + tid];

    // ---- Phase 1: AsumT[j][i] = sum_r adj[r][i][j] / (rowsum[r][i]+1) ----
    {
        float a_acc[9];
        #pragma unroll
        for (int t = 0; t < 9; t++) a_acc[t] = 0.f;
        const float* adjb = adj + (size_t)b * 6912;
        for (int r = 0; r < 3; r++) {
            __syncthreads();
            const float4* a4 = (const float4*)(adjb + r * 2304);
            float4* p4 = (float4*)s_buf;
            for (int i = tid; i < 576; i += NTHREADS) p4[i] = a4[i];
            __syncthreads();
            if (tid < 48) {
                const float4* row = (const float4*)&s_buf[tid * 48];
                float s = 0.f;
                #pragma unroll
                for (int t = 0; t < 12; t++) {
                    float4 v = row[t];
                    s += (v.x + v.y) + (v.z + v.w);
                }
                s_rinv[tid] = 1.f / (s + 1.f);
            }
            __syncthreads();
            #pragma unroll
            for (int t = 0; t < 9; t++) {
                int idx = tid + t * NTHREADS;
                a_acc[t] += s_buf[idx] * s_rinv[idx / 48];
            }
        }
        __syncthreads();
        #pragma unroll
        for (int t = 0; t < 9; t++) {
            int idx = tid + t * NTHREADS;
            int i = idx / 48, j = idx - i * 48;
            s_asum[j * 48 + i] = a_acc[t];
        }
    }
    __syncthreads();

    // ---- h1 = W1[node[j]] + b1  -> s_buf as [48][HSTRIDE] ----
    for (int t = tid; t < 1536; t += NTHREADS) {
        int j = t >> 5, d4 = (t & 31) << 2;
        float4 ww = *(const float4*)&W1[s_node[j] * 128 + d4];
        float4 bb = *(const float4*)&b1[d4];
        *(float4*)&s_buf[j * HSTRIDE + d4] =
            make_float4(ww.x + bb.x, ww.y + bb.y, ww.z + bb.z, ww.w + bb.w);
    }
    __syncthreads();

    // ---- GEMM1: h = tanh(Asum @ h1 + h1), in place in s_buf ----
    // 6 warps: warp tile 16i x 64d, thread tile 4i x 8d
    {
        const bool act = (w < 6);
        const int wi = w >> 1, wd = w & 1;
        const int li = lane & 3, ld = lane >> 2;
        const int i0 = wi * 16 + li * 4;
        const int d0 = wd * 64 + ld * 8;
        u64 acc[4][4];
        #pragma unroll
        for (int r = 0; r < 4; r++)
            #pragma unroll
            for (int p = 0; p < 4; p++) acc[r][p] = 0ull;
        if (act) {
            #pragma unroll 2
            for (int j = 0; j < 48; j++) {
                float4 aT = *(const float4*)&s_asum[j * 48 + i0];
                ulonglong2 hA = *(const ulonglong2*)&s_buf[j * HSTRIDE + d0];
                ulonglong2 hB = *(const ulonglong2*)&s_buf[j * HSTRIDE + d0 + 4];
                float av[4] = {aT.x, aT.y, aT.z, aT.w};
                #pragma unroll
                for (int r = 0; r < 4; r++) {
                    u64 aa = bc2(av[r]);
                    acc[r][0] = f2fma(aa, hA.x, acc[r][0]);
                    acc[r][1] = f2fma(aa, hA.y, acc[r][1]);
                    acc[r][2] = f2fma(aa, hB.x, acc[r][2]);
                    acc[r][3] = f2fma(aa, hB.y, acc[r][3]);
                }
            }
        }
        __syncthreads();
        if (act) {
            #pragma unroll
            for (int r = 0; r < 4; r++) {
                float* row = &s_buf[(i0 + r) * HSTRIDE + d0];
                float4 r0 = *(const float4*)row;
                float4 r1 = *(const float4*)(row + 4);
                float2 a0 = up2(acc[r][0]), a1 = up2(acc[r][1]);
                float2 a2 = up2(acc[r][2]), a3 = up2(acc[r][3]);
                *(float4*)row = make_float4(ftanh(a0.x + r0.x), ftanh(a0.y + r0.y),
                                            ftanh(a1.x + r0.z), ftanh(a1.y + r0.w));
                *(float4*)(row + 4) = make_float4(ftanh(a2.x + r1.x), ftanh(a2.y + r1.y),
                                                  ftanh(a3.x + r1.z), ftanh(a3.y + r1.w));
            }
        }
    }
    __syncthreads();

    // ---- GEMM2: h2 = h @ W2 + b2 -> s_h2 [48][64] ----
    // 6 warps: warp tile 16i x 32d, thread tile 4i x 4d
    if (w < 6) {
        const int wi = w >> 1, wd = w & 1;
        const int li = lane & 3, ld = lane >> 2;
        const int i0 = wi * 16 + li * 4;
        const int d0 = wd * 32 + ld * 4;
        float4 bv = *(const float4*)&b2[d0];
        u64 acc[4][2];
        #pragma unroll
        for (int r = 0; r < 4; r++) { acc[r][0] = pk2(bv.x, bv.y); acc[r][1] = pk2(bv.z, bv.w); }
        #pragma unroll 2
        for (int k4 = 0; k4 < 32; k4++) {
            float hr[4][4];
            #pragma unroll
            for (int r = 0; r < 4; r++) {
                float4 hv = *(const float4*)&s_buf[(i0 + r) * HSTRIDE + k4 * 4];
                hr[r][0] = hv.x; hr[r][1] = hv.y; hr[r][2] = hv.z; hr[r][3] = hv.w;
            }
            #pragma unroll
            for (int kk = 0; kk < 4; kk++) {
                ulonglong2 wrow = *(const ulonglong2*)&W2[(k4 * 4 + kk) * 64 + d0];
                #pragma unroll
                for (int r = 0; r < 4; r++) {
                    u64 hb = bc2(hr[r][kk]);
                    acc[r][0] = f2fma(hb, wrow.x, acc[r][0]);
                    acc[r][1] = f2fma(hb, wrow.y, acc[r][1]);
                }
            }
        }
        #pragma unroll
        for (int r = 0; r < 4; r++) {
            float2 a0 = up2(acc[r][0]), a1 = up2(acc[r][1]);
            *(float4*)&s_h2[(i0 + r) * 64 + d0] = make_float4(a0.x, a0.y, a1.x, a1.y);
        }
    }
    __syncthreads();

    // ---- GEMM3: h_outT[d][i] = tanh(Asum @ h2 + h2) -> s_buf [64][TSTRIDE] ----
    // 6 warps: warp tile 16i x 32d, thread tile 4i x 4d; h (s_buf as h1/h) is dead.
    if (w < 6) {
        const int wi = w >> 1, wd = w & 1;
        const int li = lane & 3, ld = lane >> 2;
        const int i0 = wi * 16 + li * 4;
        const int d0 = wd * 32 + ld * 4;
        u64 acc[4][2];
        #pragma unroll
        for (int r = 0; r < 4; r++) { acc[r][0] = 0ull; acc[r][1] = 0ull; }
        #pragma unroll 2
        for (int j = 0; j < 48; j++) {
            float4 aT = *(const float4*)&s_asum[j * 48 + i0];
            ulonglong2 hv = *(const ulonglong2*)&s_h2[j * 64 + d0];
            float av[4] = {aT.x, aT.y, aT.z, aT.w};
            #pragma unroll
            for (int r = 0; r < 4; r++) {
                u64 aa = bc2(av[r]);
                acc[r][0] = f2fma(aa, hv.x, acc[r][0]);
                acc[r][1] = f2fma(aa, hv.y, acc[r][1]);
            }
        }
        float t[4][4];
        #pragma unroll
        for (int r = 0; r < 4; r++) {
            float4 res = *(const float4*)&s_h2[(i0 + r) * 64 + d0];
            float2 a0 = up2(acc[r][0]), a1 = up2(acc[r][1]);
            t[r][0] = ftanh(a0.x + res.x);
            t[r][1] = ftanh(a0.y + res.y);
            t[r][2] = ftanh(a1.x + res.z);
            t[r][3] = ftanh(a1.y + res.w);
        }
        // transposed store, stride TSTRIDE, float2 along i (8B aligned)
        #pragma unroll
        for (int c = 0; c < 4; c++) {
            *(float2*)&s_buf[(d0 + c) * TSTRIDE + i0]     = make_float2(t[0][c], t[1][c]);
            *(float2*)&s_buf[(d0 + c) * TSTRIDE + i0 + 2] = make_float2(t[2][c], t[3][c]);
        }
    }
    __syncthreads();

    // ---- Gate: S/T GEMMs (48x128, K=64) + fused sigmoid/tanh + node reduction ----
    // 8 warps: warp tile 24i x 32d, thread tile 6i x 4d (both S and T)
    {
        const int wi = w >> 2, wd = w & 3;
        const int li = lane >> 3, ld = lane & 7;
        const int i0 = wi * 24 + li * 6;
        const int d0 = wd * 32 + ld * 4;
        u64 aS[6][2], aT6[6][2];
        #pragma unroll
        for (int ii = 0; ii < 6; ii++) {
            aS[ii][0] = 0ull; aS[ii][1] = 0ull;
            aT6[ii][0] = 0ull; aT6[ii][1] = 0ull;
        }
        for (int k = 0; k < 64; k++) {
            const float* hrow = &s_buf[k * TSTRIDE + i0];
            float2 h01 = *(const float2*)hrow;
            float2 h23 = *(const float2*)(hrow + 2);
            float2 h45 = *(const float2*)(hrow + 4);
            ulonglong2 ws = *(const ulonglong2*)&asW[k * 128 + d0];
            ulonglong2 wt = *(const ulonglong2*)&atW[k * 128 + d0];
            float hv[6] = {h01.x, h01.y, h23.x, h23.y, h45.x, h45.y};
            #pragma unroll
            for (int ii = 0; ii < 6; ii++) {
                u64 hb = bc2(hv[ii]);
                aS[ii][0]  = f2fma(hb, ws.x, aS[ii][0]);
                aS[ii][1]  = f2fma(hb, ws.y, aS[ii][1]);
                aT6[ii][0] = f2fma(hb, wt.x, aT6[ii][0]);
                aT6[ii][1] = f2fma(hb, wt.y, aT6[ii][1]);
            }
        }
        float4 sbv = *(const float4*)&asb[d0];
        float4 tbv = *(const float4*)&atb[d0];
        float sum0 = 0.f, sum1 = 0.f, sum2 = 0.f, sum3 = 0.f;
        #pragma unroll
        for (int ii = 0; ii < 6; ii++) {
            int nd = s_node[i0 + ii];
            float4 wso = *(const float4*)&asW[(64 + nd) * 128 + d0];
            float4 wto = *(const float4*)&atW[(64 + nd) * 128 + d0];
            float2 s01 = up2(aS[ii][0]), s23 = up2(aS[ii][1]);
            float2 t01 = up2(aT6[ii][0]), t23 = up2(aT6[ii][1]);
            sum0 += fsig(s01.x + wso.x + sbv.x) * ftanh(t01.x + wto.x + tbv.x);
            sum1 += fsig(s01.y + wso.y + sbv.y) * ftanh(t01.y + wto.y + tbv.y);
            sum2 += fsig(s23.x + wso.z + sbv.z) * ftanh(t23.x + wto.z + tbv.z);
            sum3 += fsig(s23.y + wso.w + sbv.w) * ftanh(t23.y + wto.w + tbv.w);
        }
        *(float4*)&s_gp[(wi * 4 + li) * 128 + d0] = make_float4(sum0, sum1, sum2, sum3);
    }
    __syncthreads();
    if (tid < 128) {
        float s = 0.f;
        #pragma unroll
        for (int r = 0; r < 8; r++) s += s_gp[r * 128 + tid];
        s_g[tid] = ftanh(s);
    }
    __syncthreads();

    // ---- hfeat = (g @ l1W + l1b) @ l2W + l2b  (k-split matvecs) ----
    {
        int c = tid & 127, half = tid >> 7;
        float acc = 0.f;
        int k0 = half * 64;
        #pragma unroll 4
        for (int k = 0; k < 64; k++) acc += s_g[k0 + k] * l1W[(k0 + k) * 128 + c];
        s_gp[half * 128 + c] = acc;
    }
    __syncthreads();
    if (tid < 128) s_t1[tid] = l1b[tid] + s_gp[tid] + s_gp[128 + tid];
    __syncthreads();
    {
        int c = tid & 63, qq = tid >> 6;
        float acc = 0.f;
        int k0 = qq * 32;
        #pragma unroll 4
        for (int k = 0; k < 32; k++) acc += s_t1[k0 + k] * l2W[(k0 + k) * 64 + c];
        s_gp[qq * 64 + c] = acc;
    }
    __syncthreads();
    if (tid < 64)
        s_hf[tid] = l2b[tid] + s_gp[tid] + s_gp[64 + tid] + s_gp[128 + tid] + s_gp[192 + tid];
    __syncthreads();

    // ---- Heads stage A: five 64->32 matvecs with leaky-relu ----
    if (tid < 160) {
        const int head = tid >> 5, u = tid & 31;
        const float* Wm;
        float acc;
        if      (head == 0) { Wm = f1;  acc = 0.f; }
        else if (head == 1) { Wm = s1;  acc = 0.f; }
        else if (head == 2) { Wm = e1;  acc = 0.f; }
        else if (head == 3) { Wm = t1W; acc = t1b[u]; }
        else                { Wm = v1W; acc = v1b[u]; }
        #pragma unroll 4
        for (int k = 0; k < 64; k++) acc += s_hf[k] * Wm[k * 32 + u];
        s_hid[tid] = lrelu(acc);
    }
    __syncthreads();

    // ---- Heads stage B ----
    if (tid < 56) {
        float acc = 0.f;
        #pragma unroll
        for (int u = 0; u < 32; u++) acc += s_hid[u] * f2[u * 56 + tid];
        bool ex = (s_node[tid] > 0) && (tid < 48);
        s_o1[tid] = acc + (ex ? 0.f : -10000.f);
    } else if (tid < 112) {
        int j = tid - 56;
        float acc = 0.f;
        #pragma unroll
        for (int u = 0; u < 32; u++) acc += s_hid[32 + u] * s2[u * 56 + j];
        s_o2[j] = acc;
    } else if (tid < 115) {
        int j = tid - 112;
        float acc = 0.f;
        #pragma unroll
        for (int u = 0; u < 32; u++) acc += s_hid[64 + u] * e2[u * 3 + j];
        s_oe[j] = acc;
    } else if (tid < 117) {
        int j = tid - 115;
        float acc = t2b[j];
        #pragma unroll
        for (int u = 0; u < 32; u++) acc += s_hid[96 + u] * t2W[u * 2 + j];
        s_ot[j] = acc;
    } else if (tid < 133) {
        int m = tid - 117;
        float acc = v2b[m];
        #pragma unroll
        for (int u = 0; u < 32; u++) acc += s_hid[128 + u] * v2W[u * 16 + m];
        s_v2[m] = lrelu(acc);
    }
    __syncthreads();

    // ---- Softmaxes / argmax / value ----
    if (tid == 0) {
        float acc = v3b[0];
        #pragma unroll
        for (int m = 0; m < 16; m++) acc += s_v2[m] * v3W[m];
        s_misc[0] = acc;                       // value

        float mx = s_o1[0]; int am = 0;        // argmax (first-max tie-break)
        for (int j = 1; j < 56; j++) { float v = s_o1[j]; if (v > mx) { mx = v; am = j; } }
        s_misc[1] = mx;
        ((int*)s_misc)[2] = am;

        float me = fmaxf(s_oe[0], fmaxf(s_oe[1], s_oe[2]));
        float e0 = __expf(s_oe[0] - me), e1v = __expf(s_oe[1] - me), e2v = __expf(s_oe[2] - me);
        float inv = 1.f / (e0 + e1v + e2v);
        s_oe[0] = e0 * inv; s_oe[1] = e1v * inv; s_oe[2] = e2v * inv;

        float mt = fmaxf(s_ot[0], s_ot[1]);
        float p0 = __expf(s_ot[0] - mt), p1 = __expf(s_ot[1] - mt);
        float invt = 1.f / (p0 + p1);
        s_ot[0] = p0 * invt; s_ot[1] = p1 * invt;
    }
    __syncthreads();
    {
        int first = ((int*)s_misc)[2];
        if (tid < 56) {
            s_o1[tid] = __expf(s_o1[tid] - s_misc[1]);
            bool ex2 = ((((s_node[tid] > 0) && (tid < 48)) || (tid >= 48)) && (tid != first));
            s_o2[tid] += (ex2 ? 0.f : -10000.f);
        }
    }
    __syncthreads();
    if (tid == 0) {
        float s = 0.f;
        for (int j = 0; j < 56; j++) s += s_o1[j];
        s_misc[3] = 1.f / s;
        float mx = s_o2[0];
        for (int j = 1; j < 56; j++) mx = fmaxf(mx, s_o2[j]);
        s_misc[4] = mx;
    }
    __syncthreads();
    if (tid < 56) s_o2[tid] = __expf(s_o2[tid] - s_misc[4]);
    __syncthreads();
    if (tid == 0) {
        float s = 0.f;
        for (int j = 0; j < 56; j++) s += s_o2[j];
        s_misc[5] = 1.f / s;
    }
    __syncthreads();

    float* ob = out + (size_t)b * 118;
    if (tid < 56) {
        ob[tid] = s_o1[tid] * s_misc[3];
    } else if (tid >= 64 && tid < 120) {
        int j = tid - 64;
        ob[56 + j] = s_o2[j] * s_misc[5];
    } else if (tid == 128) {
        ob[112] = s_oe[0]; ob[113] = s_oe[1]; ob[114] = s_oe[2];
        ob[115] = s_ot[0]; ob[116] = s_ot[1]; ob[117] = s_misc[0];
    }
}

extern "C" void kernel_launch(void* const* d_in, const int* in_sizes, int n_in,
                              void* d_out, int out_size) {
    (void)in_sizes; (void)n_in; (void)out_size;
    policy_kernel<<<8192, NTHREADS>>>(
        (const int*)  d_in[0],  (const float*)d_in[1],
        (const float*)d_in[2],  (const float*)d_in[3],
        (const float*)d_in[4],  (const float*)d_in[5],
        (const float*)d_in[6],  (const float*)d_in[7],
        (const float*)d_in[8],  (const float*)d_in[9],
        (const float*)d_in[10], (const float*)d_in[11],
        (const float*)d_in[12], (const float*)d_in[13],
        (const float*)d_in[14], (const float*)d_in[15],
        (const float*)d_in[16], (const float*)d_in[17],
        (const float*)d_in[18], (const float*)d_in[19],
        (const float*)d_in[20], (const float*)d_in[21],
        (const float*)d_in[22], (const float*)d_in[23],
        (const float*)d_in[24], (const float*)d_in[25],
        (const float*)d_in[26], (const float*)d_in[27],
        (const float*)d_in[28], (const float*)d_in[29],
        (float*)d_out);
}